// round 4
// baseline (speedup 1.0000x reference)
#include <cuda_runtime.h>
#include <math.h>

// Problem constants
#define BATCH 4
#define DMODEL 1024
#define SEQ 2048
#define NHEAD 16
#define HDIM 64
#define NTOK (BATCH * SEQ)   // 8192

// -------------------- scratch (device globals; no allocation) --------------------
__device__ float g_freq[DMODEL / 2];                       // PE frequencies
__device__ float g_xe[(size_t)NTOK * DMODEL];              // x + PE, [b,s,d]  (32 MB)
__device__ float g_q[(size_t)NTOK * DMODEL];               // [b,h,s,hd]       (32 MB)
__device__ float g_k[(size_t)NTOK * DMODEL];               // [b,h,s,hd]       (32 MB)
__device__ float g_v[(size_t)NTOK * DMODEL];               // [b,h,s,hd]       (32 MB)
__device__ float g_ao[(size_t)NTOK * DMODEL];              // attn out, [b,s,d](32 MB)

// -------------------- PE frequency init (double exp, 512 elems, trivial) --------
__global__ void k_init_freq() {
    int i = threadIdx.x;
    if (i < DMODEL / 2) {
        // denom = exp(-(2i) * ln(10000)/D), correctly rounded to fp32
        g_freq[i] = (float)exp(-(double)(2 * i) * (9.210340371976184 / 1024.0));
    }
}

// -------------------- x + PE, transpose [B,D,S] -> [B,S,D] -----------------------
__global__ void k_pe_transpose(const float* __restrict__ x) {
    __shared__ float tile[32][33];
    int b  = blockIdx.z;
    int d0 = blockIdx.y * 32;
    int s0 = blockIdx.x * 32;
    int txx = threadIdx.x, tyy = threadIdx.y;
    const float* xb = x + (size_t)b * DMODEL * SEQ;
#pragma unroll
    for (int r = 0; r < 4; r++) {
        int d = d0 + tyy + r * 8;
        int s = s0 + txx;
        float freq = g_freq[d >> 1];
        float ang  = (float)s * freq;              // fp32 mul, matches JAX pipeline
        float pe   = (d & 1) ? cosf(ang) : sinf(ang);
        tile[tyy + r * 8][txx] = xb[(size_t)d * SEQ + s] + pe;
    }
    __syncthreads();
#pragma unroll
    for (int r = 0; r < 4; r++) {
        int sl = tyy + r * 8;
        g_xe[((size_t)b * SEQ + s0 + sl) * DMODEL + d0 + txx] = tile[txx][sl];
    }
}

// -------------------- SGEMM mainloop (128x128x8, 8x8/thread) --------------------
// Computes acc[8][8] for C[m0+ty*8+i][n0+tx*8+j] = sum_k A[m][k] * W[n][k]
#define GEMM_MAINLOOP(APTR, WPTR)                                              \
    __shared__ float As[8][128];                                               \
    __shared__ float Bs[8][128];                                               \
    int tid = threadIdx.x;                                                     \
    int tx = tid & 15, ty = tid >> 4;                                          \
    int n0 = blockIdx.x * 128, m0 = blockIdx.y * 128;                          \
    int lr = tid >> 1;                                                         \
    int lc = (tid & 1) * 4;                                                    \
    const float* ap = (APTR) + (size_t)(m0 + lr) * DMODEL + lc;                \
    const float* wp = (WPTR) + (size_t)(n0 + lr) * DMODEL + lc;                \
    float acc[8][8];                                                           \
    _Pragma("unroll") for (int i = 0; i < 8; i++)                              \
        _Pragma("unroll") for (int j = 0; j < 8; j++) acc[i][j] = 0.0f;        \
    float4 av = *(const float4*)ap;                                            \
    float4 wv = *(const float4*)wp;                                            \
    for (int k0 = 0; k0 < DMODEL; k0 += 8) {                                   \
        __syncthreads();                                                       \
        As[lc + 0][lr] = av.x; As[lc + 1][lr] = av.y;                          \
        As[lc + 2][lr] = av.z; As[lc + 3][lr] = av.w;                          \
        Bs[lc + 0][lr] = wv.x; Bs[lc + 1][lr] = wv.y;                          \
        Bs[lc + 2][lr] = wv.z; Bs[lc + 3][lr] = wv.w;                          \
        __syncthreads();                                                       \
        if (k0 + 8 < DMODEL) {                                                 \
            av = *(const float4*)(ap + k0 + 8);                                \
            wv = *(const float4*)(wp + k0 + 8);                                \
        }                                                                      \
        _Pragma("unroll") for (int kk = 0; kk < 8; kk++) {                     \
            float ar[8], br[8];                                                \
            *(float4*)&ar[0] = *(const float4*)&As[kk][ty * 8];                \
            *(float4*)&ar[4] = *(const float4*)&As[kk][ty * 8 + 4];            \
            *(float4*)&br[0] = *(const float4*)&Bs[kk][tx * 8];                \
            *(float4*)&br[4] = *(const float4*)&Bs[kk][tx * 8 + 4];            \
            _Pragma("unroll") for (int i = 0; i < 8; i++)                      \
                _Pragma("unroll") for (int j = 0; j < 8; j++)                  \
                    acc[i][j] += ar[i] * br[j];                                \
        }                                                                      \
    }

// QKV projection: A = g_xe [NTOK, D]; out scattered to [b,h,s,hd]
__global__ __launch_bounds__(256) void k_gemm_qkv(const float* __restrict__ W,
                                                  const float* __restrict__ bias,
                                                  int which) {
    float* out = (which == 0) ? g_q : (which == 1) ? g_k : g_v;
    GEMM_MAINLOOP(g_xe, W)
#pragma unroll
    for (int i = 0; i < 8; i++) {
        int row = m0 + ty * 8 + i;
        int bb = row >> 11;            // / SEQ
        int s  = row & (SEQ - 1);
#pragma unroll
        for (int j4 = 0; j4 < 8; j4 += 4) {
            int jg = n0 + tx * 8 + j4;
            int h  = jg >> 6;
            int hd = jg & 63;
            float4 o;
            o.x = acc[i][j4 + 0] + bias[jg + 0];
            o.y = acc[i][j4 + 1] + bias[jg + 1];
            o.z = acc[i][j4 + 2] + bias[jg + 2];
            o.w = acc[i][j4 + 3] + bias[jg + 3];
            *(float4*)&out[(((size_t)(bb * NHEAD + h) * SEQ + s) * HDIM) + hd] = o;
        }
    }
}

// Output projection: A = g_ao [NTOK, D]; out transposed to [B, D, S]
__global__ __launch_bounds__(256) void k_gemm_out(const float* __restrict__ W,
                                                  const float* __restrict__ bias,
                                                  float* __restrict__ out) {
    GEMM_MAINLOOP(g_ao, W)
#pragma unroll
    for (int j = 0; j < 8; j++) {
        int jg = n0 + tx * 8 + j;
        float bv = bias[jg];
#pragma unroll
        for (int i4 = 0; i4 < 8; i4 += 4) {
            int row = m0 + ty * 8 + i4;
            int bb = row >> 11;
            int s  = row & (SEQ - 1);
            float4 o;
            o.x = acc[i4 + 0][j] + bv;
            o.y = acc[i4 + 1][j] + bv;
            o.z = acc[i4 + 2][j] + bv;
            o.w = acc[i4 + 3][j] + bv;
            *(float4*)&out[((size_t)bb * DMODEL + jg) * SEQ + s] = o;
        }
    }
}

// -------------------- flash attention (fp32, Br=Bc=64) ---------------------------
// grid: (SEQ/64, B*H), block 256 (16x16 logical). Smem: Qt 16K + K/P union 16K + V 16K = 48K.
__global__ __launch_bounds__(256) void k_flash() {
    __shared__ float Qt[64 * 64];   // [k][r]  (transposed Q, pre-scaled by 0.125)
    __shared__ float KP[64 * 64];   // K as [k][c]; reused as P as [c][r]
    __shared__ float Vs[64 * 64];   // [kc][c]

    int tid = threadIdx.x;
    int tx = tid & 15, ty = tid >> 4;
    int bh = blockIdx.y;
    int q0 = blockIdx.x * 64;
    const float* qp = g_q + ((size_t)bh * SEQ + q0) * HDIM;
    const float* kp = g_k + (size_t)bh * SEQ * HDIM;
    const float* vp = g_v + (size_t)bh * SEQ * HDIM;

    // Load Q tile transposed, scale by 1/sqrt(hd) = 0.125 (exact)
    {
        int r  = tid >> 2;
        int c0 = (tid & 3) * 16;
#pragma unroll
        for (int u = 0; u < 4; u++) {
            float4 v = *(const float4*)(qp + (size_t)r * HDIM + c0 + u * 4);
            Qt[(c0 + u * 4 + 0) * 64 + r] = v.x * 0.125f;
            Qt[(c0 + u * 4 + 1) * 64 + r] = v.y * 0.125f;
            Qt[(c0 + u * 4 + 2) * 64 + r] = v.z * 0.125f;
            Qt[(c0 + u * 4 + 3) * 64 + r] = v.w * 0.125f;
        }
    }

    float m_i[4], l_i[4], acc[16];
#pragma unroll
    for (int i = 0; i < 4; i++) { m_i[i] = -1e30f; l_i[i] = 0.0f; }
#pragma unroll
    for (int i = 0; i < 16; i++) acc[i] = 0.0f;

    for (int kt = 0; kt < SEQ / 64; kt++) {
        const float* kb = kp + (size_t)kt * 64 * HDIM;
        const float* vb = vp + (size_t)kt * 64 * HDIM;
        // Load K transposed into KP
        {
            int r  = tid >> 2;
            int c0 = (tid & 3) * 16;
#pragma unroll
            for (int u = 0; u < 4; u++) {
                float4 v = *(const float4*)(kb + (size_t)r * HDIM + c0 + u * 4);
                KP[(c0 + u * 4 + 0) * 64 + r] = v.x;
                KP[(c0 + u * 4 + 1) * 64 + r] = v.y;
                KP[(c0 + u * 4 + 2) * 64 + r] = v.z;
                KP[(c0 + u * 4 + 3) * 64 + r] = v.w;
            }
        }
        // Load V flat (layout matches)
#pragma unroll
        for (int u = 0; u < 4; u++) {
            float4 v = *(const float4*)(vb + (size_t)(u * 256 + tid) * 4);
            *(float4*)&Vs[(u * 256 + tid) * 4] = v;
        }
        __syncthreads();

        // S = Q K^T  (scaled): s[i][j] for rows ty*4+i, cols tx*4+j
        float sv[16];
#pragma unroll
        for (int i = 0; i < 16; i++) sv[i] = 0.0f;
#pragma unroll 16
        for (int k = 0; k < 64; k++) {
            float4 a = *(const float4*)&Qt[k * 64 + ty * 4];
            float4 b = *(const float4*)&KP[k * 64 + tx * 4];
            float ar[4] = {a.x, a.y, a.z, a.w};
            float br[4] = {b.x, b.y, b.z, b.w};
#pragma unroll
            for (int i = 0; i < 4; i++)
#pragma unroll
                for (int j = 0; j < 4; j++) sv[i * 4 + j] += ar[i] * br[j];
        }

        // Online softmax update (row groups = 16 lanes within each warp half)
#pragma unroll
        for (int i = 0; i < 4; i++) {
            float rm = fmaxf(fmaxf(sv[i * 4 + 0], sv[i * 4 + 1]),
                             fmaxf(sv[i * 4 + 2], sv[i * 4 + 3]));
#pragma unroll
            for (int off = 1; off < 16; off <<= 1)
                rm = fmaxf(rm, __shfl_xor_sync(0xffffffffu, rm, off));
            float mn = fmaxf(m_i[i], rm);
            float alpha = __expf(m_i[i] - mn);
            m_i[i] = mn;
            float rs = 0.0f;
#pragma unroll
            for (int j = 0; j < 4; j++) {
                sv[i * 4 + j] = __expf(sv[i * 4 + j] - mn);
                rs += sv[i * 4 + j];
            }
#pragma unroll
            for (int off = 1; off < 16; off <<= 1)
                rs += __shfl_xor_sync(0xffffffffu, rs, off);
            l_i[i] = l_i[i] * alpha + rs;
#pragma unroll
            for (int j = 0; j < 4; j++) acc[i * 4 + j] *= alpha;
        }
        __syncthreads();   // all reads of KP (as K) done

        // Write P transposed into KP: KP[c][r]
#pragma unroll
        for (int j = 0; j < 4; j++) {
            float4 pv = make_float4(sv[0 * 4 + j], sv[1 * 4 + j],
                                    sv[2 * 4 + j], sv[3 * 4 + j]);
            *(float4*)&KP[(tx * 4 + j) * 64 + ty * 4] = pv;
        }
        __syncthreads();

        // O += P V
#pragma unroll 16
        for (int kc = 0; kc < 64; kc++) {
            float4 a = *(const float4*)&KP[kc * 64 + ty * 4];
            float4 b = *(const float4*)&Vs[kc * 64 + tx * 4];
            float ar[4] = {a.x, a.y, a.z, a.w};
            float br[4] = {b.x, b.y, b.z, b.w};
#pragma unroll
            for (int i = 0; i < 4; i++)
#pragma unroll
                for (int j = 0; j < 4; j++) acc[i * 4 + j] += ar[i] * br[j];
        }
        __syncthreads();   // before next tile's loads overwrite KP/Vs
    }

    // Normalize and write to g_ao in [b, s, d] layout
    int bb = bh >> 4;         // / NHEAD
    int h  = bh & 15;
#pragma unroll
    for (int i = 0; i < 4; i++) {
        float inv = 1.0f / l_i[i];
        int row = q0 + ty * 4 + i;
        float4 o;
        o.x = acc[i * 4 + 0] * inv;
        o.y = acc[i * 4 + 1] * inv;
        o.z = acc[i * 4 + 2] * inv;
        o.w = acc[i * 4 + 3] * inv;
        *(float4*)&g_ao[((size_t)(bb * SEQ + row)) * DMODEL + h * HDIM + tx * 4] = o;
    }
}

// -------------------- launch --------------------------------------------------
extern "C" void kernel_launch(void* const* d_in, const int* in_sizes, int n_in,
                              void* d_out, int out_size) {
    (void)in_sizes; (void)n_in; (void)out_size;
    const float* x  = (const float*)d_in[0];
    const float* Wq = (const float*)d_in[1];
    const float* bq = (const float*)d_in[2];
    const float* Wk = (const float*)d_in[3];
    const float* bk = (const float*)d_in[4];
    const float* Wv = (const float*)d_in[5];
    const float* bv = (const float*)d_in[6];
    const float* Wo = (const float*)d_in[7];
    const float* bo = (const float*)d_in[8];
    float* out = (float*)d_out;

    k_init_freq<<<1, 512>>>();
    k_pe_transpose<<<dim3(SEQ / 32, DMODEL / 32, BATCH), dim3(32, 8)>>>(x);
    dim3 ggrid(DMODEL / 128, NTOK / 128);
    k_gemm_qkv<<<ggrid, 256>>>(Wq, bq, 0);
    k_gemm_qkv<<<ggrid, 256>>>(Wk, bk, 1);
    k_gemm_qkv<<<ggrid, 256>>>(Wv, bv, 2);
    k_flash<<<dim3(SEQ / 64, BATCH * NHEAD), 256>>>();
    k_gemm_out<<<ggrid, 256>>>(Wo, bo, out);
}

// round 8
// speedup vs baseline: 2.6938x; 2.6938x over previous
#include <cuda_runtime.h>
#include <cuda_bf16.h>
#include <cstdint>
#include <math.h>

#define BATCH 4
#define DMODEL 1024
#define SEQ 2048
#define NHEAD 16
#define HDIM 64
#define NTOK (BATCH * SEQ)   // 8192

// ===================== device scratch (no allocation) =====================
__device__ float g_freq[DMODEL / 2];
__device__ __align__(16) __nv_bfloat16 g_xhi[(size_t)NTOK * DMODEL];  // x+PE hi; later attn-out hi
__device__ __align__(16) __nv_bfloat16 g_xlo[(size_t)NTOK * DMODEL];  // x+PE lo; later attn-out lo
__device__ __align__(16) __nv_bfloat16 g_whi[4][(size_t)DMODEL * DMODEL];
__device__ __align__(16) __nv_bfloat16 g_wlo[4][(size_t)DMODEL * DMODEL];
__device__ __align__(16) float g_q[(size_t)NTOK * DMODEL];
__device__ __align__(16) float g_k[(size_t)NTOK * DMODEL];
__device__ __align__(16) float g_v[(size_t)NTOK * DMODEL];

// ===================== PTX helpers (family-agnostic: ldmatrix + mma.sync) ========
__device__ __forceinline__ uint32_t smem_u32(const void* p) {
    uint32_t a;
    asm("{ .reg .u64 t; cvta.to.shared.u64 t, %1; cvt.u32.u64 %0, t; }" : "=r"(a) : "l"(p));
    return a;
}
__device__ __forceinline__ void ldmx4(uint32_t* r, uint32_t addr) {
    asm volatile("ldmatrix.sync.aligned.m8n8.x4.shared.b16 {%0,%1,%2,%3}, [%4];"
                 : "=r"(r[0]), "=r"(r[1]), "=r"(r[2]), "=r"(r[3]) : "r"(addr));
}
__device__ __forceinline__ void mma16816(float* d, const uint32_t* a, const uint32_t* b) {
    asm volatile("mma.sync.aligned.m16n8k16.row.col.f32.bf16.bf16.f32 "
                 "{%0,%1,%2,%3}, {%4,%5,%6,%7}, {%8,%9}, {%0,%1,%2,%3};"
                 : "+f"(d[0]), "+f"(d[1]), "+f"(d[2]), "+f"(d[3])
                 : "r"(a[0]), "r"(a[1]), "r"(a[2]), "r"(a[3]), "r"(b[0]), "r"(b[1]));
}

// ===================== prep kernels =====================
__global__ void k_init_freq() {
    int i = threadIdx.x;
    if (i < DMODEL / 2)
        g_freq[i] = (float)exp(-(double)(2 * i) * (9.210340371976184 / 1024.0));
}

// x + PE, transpose [B,D,S] -> [B,S,D], write bf16 hi/lo split
__global__ void k_pe_split(const float* __restrict__ x) {
    __shared__ float tile[32][33];
    int b = blockIdx.z, d0 = blockIdx.y * 32, s0 = blockIdx.x * 32;
    int txx = threadIdx.x, tyy = threadIdx.y;
    const float* xb = x + (size_t)b * DMODEL * SEQ;
#pragma unroll
    for (int r = 0; r < 4; r++) {
        int d = d0 + tyy + r * 8, s = s0 + txx;
        float ang = (float)s * g_freq[d >> 1];
        float pe = (d & 1) ? cosf(ang) : sinf(ang);
        tile[tyy + r * 8][txx] = xb[(size_t)d * SEQ + s] + pe;
    }
    __syncthreads();
#pragma unroll
    for (int r = 0; r < 4; r++) {
        int sl = tyy + r * 8;
        float v = tile[txx][sl];
        __nv_bfloat16 hi = __float2bfloat16(v);
        float lo = v - __bfloat162float(hi);
        size_t idx = ((size_t)b * SEQ + s0 + sl) * DMODEL + d0 + txx;
        g_xhi[idx] = hi;
        g_xlo[idx] = __float2bfloat16(lo);
    }
}

// Split one weight matrix into bf16 hi/lo
__global__ void k_split_w(const float* __restrict__ w, int wsel) {
    int i = (blockIdx.x * 256 + threadIdx.x) * 4;
    float4 v = *(const float4*)(w + i);
    __nv_bfloat16* hi = g_whi[wsel];
    __nv_bfloat16* lo = g_wlo[wsel];
    float a[4] = {v.x, v.y, v.z, v.w};
#pragma unroll
    for (int j = 0; j < 4; j++) {
        __nv_bfloat16 h = __float2bfloat16(a[j]);
        hi[i + j] = h;
        lo[i + j] = __float2bfloat16(a[j] - __bfloat162float(h));
    }
}

// ===================== HMMA GEMM: C[8192,1024] = A * W^T + bias ==============
// A = g_xhi/g_xlo (device globals, referenced directly — NOT kernel args).
// 3-term split precision: Ahi*Whi + Ahi*Wlo + Alo*Whi, fp32 register accumulators.
// CTA tile 128x128, K-chunk 64 bf16 (128B SW128 rows), 2-stage double buffer.
// 8 warps as 2(M) x 4(N): warp tile 64x32, 4x4 m16n8 fragments.
#define MMS_A(s) ((uint32_t)(s) * 32768u)
#define MMS_B(s) ((uint32_t)(s) * 32768u + 16384u)
#define MM_SMEM 65536

__global__ __launch_bounds__(256) void k_mm(int wsel,
                                            const float* __restrict__ bias,
                                            float* __restrict__ outp,
                                            int which) {
    extern __shared__ char smem[];
    uint32_t sb = smem_u32(smem);
    int tid = threadIdx.x;
    int warp = tid >> 5, lane = tid & 31;
    int wm = warp & 1, wn = warp >> 1;
    int n0 = blockIdx.x * 128, m0 = blockIdx.y * 128;

    const __nv_bfloat16* WH = g_whi[wsel];
    const __nv_bfloat16* WL = g_wlo[wsel];

    float acc[4][4][4];
#pragma unroll
    for (int mt = 0; mt < 4; mt++)
#pragma unroll
        for (int nt = 0; nt < 4; nt++)
#pragma unroll
            for (int e = 0; e < 4; e++) acc[mt][nt][e] = 0.0f;

    // gmem staging layout: thread -> (row = it*32 + tid>>3, col16B = tid&7)
    int ldr = tid >> 3, ldc = tid & 7;
    uint4 ra[4], rb[4];

#define MM_LDG(cgv) do {                                                        \
        int _cg = (cgv);                                                        \
        const __nv_bfloat16* Ap = (_cg < 32) ? g_xhi : g_xlo;                   \
        const __nv_bfloat16* Bp = (_cg >= 16 && _cg < 32) ? WL : WH;            \
        int _kc = _cg & 15;                                                     \
        const __nv_bfloat16* ab = Ap + (size_t)(m0 + ldr) * DMODEL + _kc * 64 + ldc * 8; \
        const __nv_bfloat16* bb = Bp + (size_t)(n0 + ldr) * DMODEL + _kc * 64 + ldc * 8; \
        _Pragma("unroll") for (int it = 0; it < 4; it++) {                      \
            ra[it] = *(const uint4*)(ab + (size_t)it * 32 * DMODEL);            \
            rb[it] = *(const uint4*)(bb + (size_t)it * 32 * DMODEL);            \
        }                                                                       \
    } while (0)

#define MM_STS(sv) do {                                                         \
        _Pragma("unroll") for (int it = 0; it < 4; it++) {                      \
            uint32_t off = (uint32_t)((it * 32 + ldr) * 128 + ldc * 16);        \
            off ^= (off >> 3) & 0x70;                                           \
            *(uint4*)(smem + MMS_A(sv) + off) = ra[it];                         \
            *(uint4*)(smem + MMS_B(sv) + off) = rb[it];                         \
        }                                                                       \
    } while (0)

    // per-thread ldmatrix row/byte components (canonical m16n8k16 fragments)
    int a_row = wm * 64 + (lane & 15);                         // + mt*16
    int a_kb = (lane >> 4) * 16;                               // + k16*32
    int b_row = wn * 32 + (lane & 7) + ((lane >> 4) & 1) * 8;  // + ntp*16
    int b_kb = ((lane >> 3) & 1) * 16;

    MM_LDG(0);
    MM_STS(0);
    __syncthreads();
    MM_LDG(1);

#pragma unroll 1
    for (int cg = 0; cg < 48; cg++) {
        int s = cg & 1;
        uint32_t sa = sb + MMS_A(s), sbb = sb + MMS_B(s);
#pragma unroll
        for (int k16 = 0; k16 < 4; k16++) {
            int kbyte = k16 * 32;
            uint32_t af[4][4], bfr[2][4];
#pragma unroll
            for (int mt = 0; mt < 4; mt++) {
                uint32_t off = (uint32_t)((a_row + mt * 16) * 128 + kbyte + a_kb);
                off ^= (off >> 3) & 0x70;
                ldmx4(af[mt], sa + off);
            }
#pragma unroll
            for (int ntp = 0; ntp < 2; ntp++) {
                uint32_t off = (uint32_t)((b_row + ntp * 16) * 128 + kbyte + b_kb);
                off ^= (off >> 3) & 0x70;
                ldmx4(bfr[ntp], sbb + off);
            }
#pragma unroll
            for (int mt = 0; mt < 4; mt++)
#pragma unroll
                for (int nt = 0; nt < 4; nt++)
                    mma16816(acc[mt][nt], af[mt], &bfr[nt >> 1][(nt & 1) * 2]);
        }
        __syncthreads();
        if (cg + 1 < 48) {
            MM_STS(s ^ 1);
            __syncthreads();
            if (cg + 2 < 48) MM_LDG(cg + 2);
        }
    }

    // ---- epilogue: d0,d1 -> (r0, c0..c0+1); d2,d3 -> (r0+8, ..)
    int r0 = lane >> 2, c0 = (lane & 3) * 2;
    int mbase = m0 + wm * 64, nbase = n0 + wn * 32;
    if (which < 3) {
        float* out = (which == 0) ? g_q : (which == 1) ? g_k : g_v;
#pragma unroll
        for (int mt = 0; mt < 4; mt++)
#pragma unroll
            for (int half = 0; half < 2; half++) {
                int row = mbase + mt * 16 + r0 + half * 8;
                int bb2 = row >> 11;
                int sq = row & (SEQ - 1);
#pragma unroll
                for (int nt = 0; nt < 4; nt++) {
                    int jg = nbase + nt * 8 + c0;
                    int h = jg >> 6, hd = jg & 63;
                    float2 o;
                    o.x = acc[mt][nt][half * 2 + 0] + bias[jg + 0];
                    o.y = acc[mt][nt][half * 2 + 1] + bias[jg + 1];
                    *(float2*)&out[(((size_t)(bb2 * NHEAD + h) * SEQ + sq) * HDIM) + hd] = o;
                }
            }
    } else {
        // final projection: out[B, D, S]
#pragma unroll
        for (int mt = 0; mt < 4; mt++)
#pragma unroll
            for (int half = 0; half < 2; half++) {
                int row = mbase + mt * 16 + r0 + half * 8;
                int bb2 = row >> 11;
                int sq = row & (SEQ - 1);
#pragma unroll
                for (int nt = 0; nt < 4; nt++) {
                    int jg = nbase + nt * 8 + c0;
                    outp[((size_t)bb2 * DMODEL + jg) * SEQ + sq] =
                        acc[mt][nt][half * 2 + 0] + bias[jg];
                    outp[((size_t)bb2 * DMODEL + jg + 1) * SEQ + sq] =
                        acc[mt][nt][half * 2 + 1] + bias[jg + 1];
                }
            }
    }
}

// ===================== flash attention (fp32, Br=128, Bc=64) =====================
// 256 threads (16x16 logical), 8x4 register tile. Dynamic smem (floats):
//   QT [64][128] @0 (32KB), KT [64][64] @8192 (16KB), VS [64][64] @12288 (16KB),
//   PS row-major [128][68] @16384 (34816B). Total 100352 B.
// PS stride 68 floats = 17 float4: write quad-bank = (i+tx) mod 8 -> conflict-free,
// 16B-aligned. Reads: P rows broadcast, V tx-distinct.
#define FL_SMEM 100352
__global__ void __launch_bounds__(256, 2) k_flash() {
    extern __shared__ float sm[];
    float* QT = sm;
    float* KT = sm + 8192;
    float* VS = sm + 12288;
    float* PS = sm + 16384;

    int tid = threadIdx.x;
    int tx = tid & 15, ty = tid >> 4;
    int bh = blockIdx.y;
    int q0 = blockIdx.x * 128;
    const float* qp = g_q + ((size_t)bh * SEQ + q0) * HDIM;
    const float* kp = g_k + (size_t)bh * SEQ * HDIM;
    const float* vp = g_v + (size_t)bh * SEQ * HDIM;

    // Q tile transposed + scaled by 1/8 (exact)
    {
        int r = tid >> 1, c0 = (tid & 1) * 32;
#pragma unroll
        for (int u = 0; u < 8; u++) {
            float4 v = *(const float4*)(qp + (size_t)r * HDIM + c0 + u * 4);
            QT[(c0 + u * 4 + 0) * 128 + r] = v.x * 0.125f;
            QT[(c0 + u * 4 + 1) * 128 + r] = v.y * 0.125f;
            QT[(c0 + u * 4 + 2) * 128 + r] = v.z * 0.125f;
            QT[(c0 + u * 4 + 3) * 128 + r] = v.w * 0.125f;
        }
    }

    float m_i[8], l_i[8], acc[32];
#pragma unroll
    for (int i = 0; i < 8; i++) { m_i[i] = -1e30f; l_i[i] = 0.0f; }
#pragma unroll
    for (int i = 0; i < 32; i++) acc[i] = 0.0f;

    for (int kt = 0; kt < SEQ / 64; kt++) {
        const float* kb = kp + (size_t)kt * 64 * HDIM;
        const float* vb = vp + (size_t)kt * 64 * HDIM;
        {   // K transposed
            int r = tid >> 2, c0 = (tid & 3) * 16;
#pragma unroll
            for (int u = 0; u < 4; u++) {
                float4 v = *(const float4*)(kb + (size_t)r * HDIM + c0 + u * 4);
                KT[(c0 + u * 4 + 0) * 64 + r] = v.x;
                KT[(c0 + u * 4 + 1) * 64 + r] = v.y;
                KT[(c0 + u * 4 + 2) * 64 + r] = v.z;
                KT[(c0 + u * 4 + 3) * 64 + r] = v.w;
            }
        }
#pragma unroll
        for (int u = 0; u < 4; u++) {
            float4 v = *(const float4*)(vb + (size_t)(u * 256 + tid) * 4);
            *(float4*)&VS[(u * 256 + tid) * 4] = v;
        }
        __syncthreads();

        // S = Q K^T : rows ty*8+i (8), cols tx*4+j (4)
        float sv[32];
#pragma unroll
        for (int i = 0; i < 32; i++) sv[i] = 0.0f;
#pragma unroll 8
        for (int k = 0; k < 64; k++) {
            float4 a0 = *(const float4*)&QT[k * 128 + ty * 8];
            float4 a1 = *(const float4*)&QT[k * 128 + ty * 8 + 4];
            float4 b = *(const float4*)&KT[k * 64 + tx * 4];
            float ar[8] = {a0.x, a0.y, a0.z, a0.w, a1.x, a1.y, a1.z, a1.w};
            float br[4] = {b.x, b.y, b.z, b.w};
#pragma unroll
            for (int i = 0; i < 8; i++)
#pragma unroll
                for (int j = 0; j < 4; j++) sv[i * 4 + j] += ar[i] * br[j];
        }

        // online softmax (16-lane row groups)
#pragma unroll
        for (int i = 0; i < 8; i++) {
            float rm = fmaxf(fmaxf(sv[i * 4 + 0], sv[i * 4 + 1]),
                             fmaxf(sv[i * 4 + 2], sv[i * 4 + 3]));
#pragma unroll
            for (int off = 1; off < 16; off <<= 1)
                rm = fmaxf(rm, __shfl_xor_sync(0xffffffffu, rm, off));
            float mn = fmaxf(m_i[i], rm);
            float alpha = __expf(m_i[i] - mn);
            m_i[i] = mn;
            float rs = 0.0f;
#pragma unroll
            for (int j = 0; j < 4; j++) {
                sv[i * 4 + j] = __expf(sv[i * 4 + j] - mn);
                rs += sv[i * 4 + j];
            }
#pragma unroll
            for (int off = 1; off < 16; off <<= 1)
                rs += __shfl_xor_sync(0xffffffffu, rs, off);
            l_i[i] = l_i[i] * alpha + rs;
#pragma unroll
            for (int j = 0; j < 4; j++) acc[i * 4 + j] *= alpha;
        }

        // write P row-major: PS[r][kc], stride 68, 16B-aligned float4
#pragma unroll
        for (int i = 0; i < 8; i++) {
            *(float4*)&PS[(ty * 8 + i) * 68 + tx * 4] =
                make_float4(sv[i * 4 + 0], sv[i * 4 + 1], sv[i * 4 + 2], sv[i * 4 + 3]);
        }
        __syncthreads();

        // O += P V  (P rows broadcast across tx; V rows tx-distinct)
#pragma unroll 4
        for (int kc4 = 0; kc4 < 16; kc4++) {
            float4 p[8];
#pragma unroll
            for (int i = 0; i < 8; i++)
                p[i] = *(const float4*)&PS[(ty * 8 + i) * 68 + kc4 * 4];
            float4 v0 = *(const float4*)&VS[(kc4 * 4 + 0) * 64 + tx * 4];
            float4 v1 = *(const float4*)&VS[(kc4 * 4 + 1) * 64 + tx * 4];
            float4 v2 = *(const float4*)&VS[(kc4 * 4 + 2) * 64 + tx * 4];
            float4 v3 = *(const float4*)&VS[(kc4 * 4 + 3) * 64 + tx * 4];
            float vr[4][4] = {{v0.x, v0.y, v0.z, v0.w}, {v1.x, v1.y, v1.z, v1.w},
                              {v2.x, v2.y, v2.z, v2.w}, {v3.x, v3.y, v3.z, v3.w}};
#pragma unroll
            for (int i = 0; i < 8; i++) {
                float pr[4] = {p[i].x, p[i].y, p[i].z, p[i].w};
#pragma unroll
                for (int t = 0; t < 4; t++)
#pragma unroll
                    for (int j = 0; j < 4; j++)
                        acc[i * 4 + j] += pr[t] * vr[t][j];
            }
        }
        __syncthreads();
    }

    // normalize, split to bf16 hi/lo, write to g_xhi/g_xlo in [b,s,d]
    int bb = bh >> 4, h = bh & 15;
#pragma unroll
    for (int i = 0; i < 8; i++) {
        float inv = 1.0f / l_i[i];
        int row = q0 + ty * 8 + i;
        size_t base = ((size_t)(bb * SEQ + row)) * DMODEL + h * HDIM + tx * 4;
#pragma unroll
        for (int j = 0; j < 4; j++) {
            float o = acc[i * 4 + j] * inv;
            __nv_bfloat16 hi = __float2bfloat16(o);
            g_xhi[base + j] = hi;
            g_xlo[base + j] = __float2bfloat16(o - __bfloat162float(hi));
        }
    }
}

// ===================== launch =====================
extern "C" void kernel_launch(void* const* d_in, const int* in_sizes, int n_in,
                              void* d_out, int out_size) {
    (void)in_sizes; (void)n_in; (void)out_size;
    const float* x  = (const float*)d_in[0];
    const float* Wq = (const float*)d_in[1];
    const float* bq = (const float*)d_in[2];
    const float* Wk = (const float*)d_in[3];
    const float* bk = (const float*)d_in[4];
    const float* Wv = (const float*)d_in[5];
    const float* bv = (const float*)d_in[6];
    const float* Wo = (const float*)d_in[7];
    const float* bo = (const float*)d_in[8];
    float* out = (float*)d_out;

    cudaFuncSetAttribute(k_mm, cudaFuncAttributeMaxDynamicSharedMemorySize, MM_SMEM);
    cudaFuncSetAttribute(k_flash, cudaFuncAttributeMaxDynamicSharedMemorySize, FL_SMEM);

    k_init_freq<<<1, 512>>>();
    k_pe_split<<<dim3(SEQ / 32, DMODEL / 32, BATCH), dim3(32, 8)>>>(x);
    k_split_w<<<1024, 256>>>(Wq, 0);
    k_split_w<<<1024, 256>>>(Wk, 1);
    k_split_w<<<1024, 256>>>(Wv, 2);
    k_split_w<<<1024, 256>>>(Wo, 3);

    dim3 ggrid(DMODEL / 128, NTOK / 128);
    k_mm<<<ggrid, 256, MM_SMEM>>>(0, bq, nullptr, 0);
    k_mm<<<ggrid, 256, MM_SMEM>>>(1, bk, nullptr, 1);
    k_mm<<<ggrid, 256, MM_SMEM>>>(2, bv, nullptr, 2);

    k_flash<<<dim3(SEQ / 128, BATCH * NHEAD), 256, FL_SMEM>>>();

    k_mm<<<ggrid, 256, MM_SMEM>>>(3, bo, out, 3);
}

// round 9
// speedup vs baseline: 4.4971x; 1.6694x over previous
#include <cuda_runtime.h>
#include <cuda_bf16.h>
#include <cstdint>
#include <math.h>

#define BATCH 4
#define DMODEL 1024
#define SEQ 2048
#define NHEAD 16
#define HDIM 64
#define NTOK (BATCH * SEQ)   // 8192

// ===================== device scratch (no allocation) =====================
__device__ float g_freq[DMODEL / 2];
__device__ __align__(16) __nv_bfloat16 g_xhi[(size_t)NTOK * DMODEL];  // x+PE hi; later attn-out hi
__device__ __align__(16) __nv_bfloat16 g_xlo[(size_t)NTOK * DMODEL];  // x+PE lo; later attn-out lo
__device__ __align__(16) __nv_bfloat16 g_whi[4][(size_t)DMODEL * DMODEL];
__device__ __align__(16) __nv_bfloat16 g_wlo[4][(size_t)DMODEL * DMODEL];
// bf16 hi/lo Q,K ([bh][s][hd], Q pre-scaled by 0.125) and V transposed ([bh][hd][s])
__device__ __align__(16) __nv_bfloat16 g_qhi[(size_t)NTOK * DMODEL];
__device__ __align__(16) __nv_bfloat16 g_qlo[(size_t)NTOK * DMODEL];
__device__ __align__(16) __nv_bfloat16 g_khi[(size_t)NTOK * DMODEL];
__device__ __align__(16) __nv_bfloat16 g_klo[(size_t)NTOK * DMODEL];
__device__ __align__(16) __nv_bfloat16 g_vthi[(size_t)NTOK * DMODEL];
__device__ __align__(16) __nv_bfloat16 g_vtlo[(size_t)NTOK * DMODEL];

// ===================== PTX helpers (family-agnostic) =====================
__device__ __forceinline__ uint32_t smem_u32(const void* p) {
    uint32_t a;
    asm("{ .reg .u64 t; cvta.to.shared.u64 t, %1; cvt.u32.u64 %0, t; }" : "=r"(a) : "l"(p));
    return a;
}
__device__ __forceinline__ void ldmx4(uint32_t* r, uint32_t addr) {
    asm volatile("ldmatrix.sync.aligned.m8n8.x4.shared.b16 {%0,%1,%2,%3}, [%4];"
                 : "=r"(r[0]), "=r"(r[1]), "=r"(r[2]), "=r"(r[3]) : "r"(addr));
}
__device__ __forceinline__ void mma16816(float* d, const uint32_t* a, const uint32_t* b) {
    asm volatile("mma.sync.aligned.m16n8k16.row.col.f32.bf16.bf16.f32 "
                 "{%0,%1,%2,%3}, {%4,%5,%6,%7}, {%8,%9}, {%0,%1,%2,%3};"
                 : "+f"(d[0]), "+f"(d[1]), "+f"(d[2]), "+f"(d[3])
                 : "r"(a[0]), "r"(a[1]), "r"(a[2]), "r"(a[3]), "r"(b[0]), "r"(b[1]));
}
__device__ __forceinline__ void cpa16(uint32_t saddr, const void* g) {
    asm volatile("cp.async.cg.shared.global [%0], [%1], 16;" :: "r"(saddr), "l"(g));
}
#define CP_COMMIT asm volatile("cp.async.commit_group;" ::: "memory")
#define CP_WAIT1 asm volatile("cp.async.wait_group 1;" ::: "memory")
#define CP_WAIT0 asm volatile("cp.async.wait_group 0;" ::: "memory")

// split fp32 pair into packed bf16x2 hi and lo (low half = first arg)
__device__ __forceinline__ void split2(float x0, float x1, uint32_t& hi, uint32_t& lo) {
    __nv_bfloat162 h = __floats2bfloat162_rn(x0, x1);
    hi = *(uint32_t*)&h;
    float r0 = x0 - __bfloat162float(h.x);
    float r1 = x1 - __bfloat162float(h.y);
    __nv_bfloat162 l = __floats2bfloat162_rn(r0, r1);
    lo = *(uint32_t*)&l;
}

// ===================== prep kernels =====================
__global__ void k_init_freq() {
    int i = threadIdx.x;
    if (i < DMODEL / 2)
        g_freq[i] = (float)exp(-(double)(2 * i) * (9.210340371976184 / 1024.0));
}

// x + PE, transpose [B,D,S] -> [B,S,D], write bf16 hi/lo split
__global__ void k_pe_split(const float* __restrict__ x) {
    __shared__ float tile[32][33];
    int b = blockIdx.z, d0 = blockIdx.y * 32, s0 = blockIdx.x * 32;
    int txx = threadIdx.x, tyy = threadIdx.y;
    const float* xb = x + (size_t)b * DMODEL * SEQ;
#pragma unroll
    for (int r = 0; r < 4; r++) {
        int d = d0 + tyy + r * 8, s = s0 + txx;
        float ang = (float)s * g_freq[d >> 1];
        float pe = (d & 1) ? cosf(ang) : sinf(ang);
        tile[tyy + r * 8][txx] = xb[(size_t)d * SEQ + s] + pe;
    }
    __syncthreads();
#pragma unroll
    for (int r = 0; r < 4; r++) {
        int sl = tyy + r * 8;
        float v = tile[txx][sl];
        __nv_bfloat16 hi = __float2bfloat16(v);
        float lo = v - __bfloat162float(hi);
        size_t idx = ((size_t)b * SEQ + s0 + sl) * DMODEL + d0 + txx;
        g_xhi[idx] = hi;
        g_xlo[idx] = __float2bfloat16(lo);
    }
}

// Split one weight matrix into bf16 hi/lo
__global__ void k_split_w(const float* __restrict__ w, int wsel) {
    int i = (blockIdx.x * 256 + threadIdx.x) * 4;
    float4 v = *(const float4*)(w + i);
    __nv_bfloat16* hi = g_whi[wsel];
    __nv_bfloat16* lo = g_wlo[wsel];
    float a[4] = {v.x, v.y, v.z, v.w};
#pragma unroll
    for (int j = 0; j < 4; j++) {
        __nv_bfloat16 h = __float2bfloat16(a[j]);
        hi[i + j] = h;
        lo[i + j] = __float2bfloat16(a[j] - __bfloat162float(h));
    }
}

// ===================== HMMA GEMM: C[8192,1024] = A * W^T + bias ==============
// A = g_xhi/g_xlo (device globals). 3-term split: Ahi*Whi + Ahi*Wlo + Alo*Whi.
// CTA tile 128x128, K-chunk 64 bf16 (128B SW128 rows), 2-stage double buffer.
#define MMS_A(s) ((uint32_t)(s) * 32768u)
#define MMS_B(s) ((uint32_t)(s) * 32768u + 16384u)
#define MM_SMEM 65536

__global__ __launch_bounds__(256) void k_mm(int wsel,
                                            const float* __restrict__ bias,
                                            float* __restrict__ outp,
                                            int which) {
    extern __shared__ char smem[];
    uint32_t sb = smem_u32(smem);
    int tid = threadIdx.x;
    int warp = tid >> 5, lane = tid & 31;
    int wm = warp & 1, wn = warp >> 1;
    int n0 = blockIdx.x * 128, m0 = blockIdx.y * 128;

    const __nv_bfloat16* WH = g_whi[wsel];
    const __nv_bfloat16* WL = g_wlo[wsel];

    float acc[4][4][4];
#pragma unroll
    for (int mt = 0; mt < 4; mt++)
#pragma unroll
        for (int nt = 0; nt < 4; nt++)
#pragma unroll
            for (int e = 0; e < 4; e++) acc[mt][nt][e] = 0.0f;

    int ldr = tid >> 3, ldc = tid & 7;
    uint4 ra[4], rb[4];

#define MM_LDG(cgv) do {                                                        \
        int _cg = (cgv);                                                        \
        const __nv_bfloat16* Ap = (_cg < 32) ? g_xhi : g_xlo;                   \
        const __nv_bfloat16* Bp = (_cg >= 16 && _cg < 32) ? WL : WH;            \
        int _kc = _cg & 15;                                                     \
        const __nv_bfloat16* ab = Ap + (size_t)(m0 + ldr) * DMODEL + _kc * 64 + ldc * 8; \
        const __nv_bfloat16* bb = Bp + (size_t)(n0 + ldr) * DMODEL + _kc * 64 + ldc * 8; \
        _Pragma("unroll") for (int it = 0; it < 4; it++) {                      \
            ra[it] = *(const uint4*)(ab + (size_t)it * 32 * DMODEL);            \
            rb[it] = *(const uint4*)(bb + (size_t)it * 32 * DMODEL);            \
        }                                                                       \
    } while (0)

#define MM_STS(sv) do {                                                         \
        _Pragma("unroll") for (int it = 0; it < 4; it++) {                      \
            uint32_t off = (uint32_t)((it * 32 + ldr) * 128 + ldc * 16);        \
            off ^= (off >> 3) & 0x70;                                           \
            *(uint4*)(smem + MMS_A(sv) + off) = ra[it];                         \
            *(uint4*)(smem + MMS_B(sv) + off) = rb[it];                         \
        }                                                                       \
    } while (0)

    int a_row = wm * 64 + (lane & 15);
    int a_kb = (lane >> 4) * 16;
    int b_row = wn * 32 + (lane & 7) + ((lane >> 4) & 1) * 8;
    int b_kb = ((lane >> 3) & 1) * 16;

    MM_LDG(0);
    MM_STS(0);
    __syncthreads();
    MM_LDG(1);

#pragma unroll 1
    for (int cg = 0; cg < 48; cg++) {
        int s = cg & 1;
        uint32_t sa = sb + MMS_A(s), sbb = sb + MMS_B(s);
#pragma unroll
        for (int k16 = 0; k16 < 4; k16++) {
            int kbyte = k16 * 32;
            uint32_t af[4][4], bfr[2][4];
#pragma unroll
            for (int mt = 0; mt < 4; mt++) {
                uint32_t off = (uint32_t)((a_row + mt * 16) * 128 + kbyte + a_kb);
                off ^= (off >> 3) & 0x70;
                ldmx4(af[mt], sa + off);
            }
#pragma unroll
            for (int ntp = 0; ntp < 2; ntp++) {
                uint32_t off = (uint32_t)((b_row + ntp * 16) * 128 + kbyte + b_kb);
                off ^= (off >> 3) & 0x70;
                ldmx4(bfr[ntp], sbb + off);
            }
#pragma unroll
            for (int mt = 0; mt < 4; mt++)
#pragma unroll
                for (int nt = 0; nt < 4; nt++)
                    mma16816(acc[mt][nt], af[mt], &bfr[nt >> 1][(nt & 1) * 2]);
        }
        __syncthreads();
        if (cg + 1 < 48) {
            MM_STS(s ^ 1);
            __syncthreads();
            if (cg + 2 < 48) MM_LDG(cg + 2);
        }
    }

    // ---- epilogue: d0,d1 -> (r0, c0..c0+1); d2,d3 -> (r0+8, ..)
    int r0 = lane >> 2, c0 = (lane & 3) * 2;
    int mbase = m0 + wm * 64, nbase = n0 + wn * 32;
    if (which <= 1) {
        // Q (scaled 0.125) or K -> bf16 hi/lo in [bh][s][hd]
        __nv_bfloat16* HI = which ? g_khi : g_qhi;
        __nv_bfloat16* LO = which ? g_klo : g_qlo;
        float scale = which ? 1.0f : 0.125f;
#pragma unroll
        for (int mt = 0; mt < 4; mt++)
#pragma unroll
            for (int half = 0; half < 2; half++) {
                int row = mbase + mt * 16 + r0 + half * 8;
                int bb2 = row >> 11;
                int sq = row & (SEQ - 1);
#pragma unroll
                for (int nt = 0; nt < 4; nt++) {
                    int jg = nbase + nt * 8 + c0;
                    int h = jg >> 6, hd = jg & 63;
                    float v0 = (acc[mt][nt][half * 2 + 0] + bias[jg + 0]) * scale;
                    float v1 = (acc[mt][nt][half * 2 + 1] + bias[jg + 1]) * scale;
                    uint32_t hi, lo;
                    split2(v0, v1, hi, lo);
                    size_t idx = ((size_t)(bb2 * NHEAD + h) * SEQ + sq) * HDIM + hd;
                    *(uint32_t*)&HI[idx] = hi;
                    *(uint32_t*)&LO[idx] = lo;
                }
            }
    } else if (which == 2) {
        // V -> bf16 hi/lo transposed [bh][hd][s]
#pragma unroll
        for (int mt = 0; mt < 4; mt++)
#pragma unroll
            for (int half = 0; half < 2; half++) {
                int row = mbase + mt * 16 + r0 + half * 8;
                int bb2 = row >> 11;
                int sq = row & (SEQ - 1);
#pragma unroll
                for (int nt = 0; nt < 4; nt++) {
                    int jg = nbase + nt * 8 + c0;
                    int h = jg >> 6, hd = jg & 63;
                    float v0 = acc[mt][nt][half * 2 + 0] + bias[jg + 0];
                    float v1 = acc[mt][nt][half * 2 + 1] + bias[jg + 1];
                    __nv_bfloat16 h0 = __float2bfloat16(v0);
                    __nv_bfloat16 h1 = __float2bfloat16(v1);
                    __nv_bfloat16 l0 = __float2bfloat16(v0 - __bfloat162float(h0));
                    __nv_bfloat16 l1 = __float2bfloat16(v1 - __bfloat162float(h1));
                    size_t tb = ((size_t)(bb2 * NHEAD + h) * HDIM + hd) * SEQ + sq;
                    g_vthi[tb] = h0; g_vtlo[tb] = l0;
                    g_vthi[tb + SEQ] = h1; g_vtlo[tb + SEQ] = l1;
                }
            }
    } else {
        // final projection: out[B, D, S]
#pragma unroll
        for (int mt = 0; mt < 4; mt++)
#pragma unroll
            for (int half = 0; half < 2; half++) {
                int row = mbase + mt * 16 + r0 + half * 8;
                int bb2 = row >> 11;
                int sq = row & (SEQ - 1);
#pragma unroll
                for (int nt = 0; nt < 4; nt++) {
                    int jg = nbase + nt * 8 + c0;
                    outp[((size_t)bb2 * DMODEL + jg) * SEQ + sq] =
                        acc[mt][nt][half * 2 + 0] + bias[jg];
                    outp[((size_t)bb2 * DMODEL + jg + 1) * SEQ + sq] =
                        acc[mt][nt][half * 2 + 1] + bias[jg + 1];
                }
            }
    }
}

// ===================== tensor-core flash attention =====================
// Br=128 (8 warps x m16), Bc=64. S = QhiKhi + QloKhi + QhiKlo (fp32 frags),
// softmax in fragments, P converted to bf16 hi/lo in registers (C->A layout match),
// O += PhiVhi + PloVhi + PhiVlo. K/V tiles cp.async double-buffered.
// smem: stage s at s*32768: KH 8K | KL 8K | VH 8K | VL 8K. Q staged at 0 in prologue.
#define FL2_SMEM 65536
__global__ __launch_bounds__(256) void k_flash2() {
    extern __shared__ char sm2[];
    uint32_t sb = smem_u32(sm2);
    int tid = threadIdx.x;
    int warp = tid >> 5, lane = tid & 31;
    int bh = blockIdx.y;
    int q0 = blockIdx.x * 128;

    const __nv_bfloat16* qh_g = g_qhi + ((size_t)bh * SEQ + q0) * HDIM;
    const __nv_bfloat16* ql_g = g_qlo + ((size_t)bh * SEQ + q0) * HDIM;
    const __nv_bfloat16* kh_g = g_khi + (size_t)bh * SEQ * HDIM;
    const __nv_bfloat16* kl_g = g_klo + (size_t)bh * SEQ * HDIM;
    const __nv_bfloat16* vh_g = g_vthi + (size_t)bh * HDIM * SEQ;
    const __nv_bfloat16* vl_g = g_vtlo + (size_t)bh * HDIM * SEQ;

    // ---- stage Q (hi @0, lo @16384), extract fragments, then free the space
#pragma unroll
    for (int it = 0; it < 4; it++) {
        int c = it * 256 + tid;
        int r = c >> 3, col = c & 7;
        uint32_t off = (uint32_t)(r * 128 + col * 16);
        off ^= (off >> 3) & 0x70;
        *(uint4*)(sm2 + off) = *(const uint4*)(qh_g + (size_t)r * HDIM + col * 8);
        *(uint4*)(sm2 + 16384 + off) = *(const uint4*)(ql_g + (size_t)r * HDIM + col * 8);
    }
    __syncthreads();
    uint32_t qh[4][4], ql[4][4];
    {
        int a_row = warp * 16 + (lane & 15);
        int a_kb = (lane >> 4) * 16;
#pragma unroll
        for (int t = 0; t < 4; t++) {
            uint32_t off = (uint32_t)(a_row * 128 + t * 32 + a_kb);
            off ^= (off >> 3) & 0x70;
            ldmx4(qh[t], sb + off);
            ldmx4(ql[t], sb + 16384 + off);
        }
    }
    __syncthreads();

    int b_row = (lane & 7) + ((lane >> 4) & 1) * 8;   // + pair*16
    int b_kb = ((lane >> 3) & 1) * 16;                // + t*32

#define FL_LOAD(s, kt) do {                                                     \
        uint32_t bs = sb + (uint32_t)(s) * 32768u;                              \
        int kb0 = (kt) * 64;                                                    \
        _Pragma("unroll") for (int it = 0; it < 2; it++) {                      \
            int c = it * 256 + tid;                                             \
            int r = c >> 3, col = c & 7;                                        \
            uint32_t off = (uint32_t)(r * 128 + col * 16);                      \
            off ^= (off >> 3) & 0x70;                                           \
            cpa16(bs + off, kh_g + (size_t)(kb0 + r) * HDIM + col * 8);         \
            cpa16(bs + 8192 + off, kl_g + (size_t)(kb0 + r) * HDIM + col * 8);  \
            cpa16(bs + 16384 + off, vh_g + (size_t)r * SEQ + kb0 + col * 8);    \
            cpa16(bs + 24576 + off, vl_g + (size_t)r * SEQ + kb0 + col * 8);    \
        }                                                                       \
    } while (0)

    float oa[8][4];
#pragma unroll
    for (int j = 0; j < 8; j++)
#pragma unroll
        for (int e = 0; e < 4; e++) oa[j][e] = 0.0f;
    float m0 = -1e30f, m1 = -1e30f, l0 = 0.0f, l1 = 0.0f;

    FL_LOAD(0, 0);
    CP_COMMIT;

#pragma unroll 1
    for (int kt = 0; kt < SEQ / 64; kt++) {
        int s = kt & 1;
        if (kt + 1 < SEQ / 64) {
            FL_LOAD(s ^ 1, kt + 1);
            CP_COMMIT;
            CP_WAIT1;
        } else {
            CP_WAIT0;
        }
        __syncthreads();
        uint32_t kh_s = sb + (uint32_t)s * 32768u;
        uint32_t kl_s = kh_s + 8192u, vh_s = kh_s + 16384u, vl_s = kh_s + 24576u;

        // ---- S = Q K^T (3-term)
        float sv[8][4];
#pragma unroll
        for (int j = 0; j < 8; j++)
#pragma unroll
            for (int e = 0; e < 4; e++) sv[j][e] = 0.0f;
#pragma unroll
        for (int t = 0; t < 4; t++) {
            uint32_t bf_[4][4];
            uint32_t offs[4];
#pragma unroll
            for (int p = 0; p < 4; p++) {
                uint32_t off = (uint32_t)((p * 16 + b_row) * 128 + t * 32 + b_kb);
                off ^= (off >> 3) & 0x70;
                offs[p] = off;
                ldmx4(bf_[p], kh_s + off);
            }
#pragma unroll
            for (int j = 0; j < 8; j++) mma16816(sv[j], qh[t], &bf_[j >> 1][(j & 1) * 2]);
#pragma unroll
            for (int j = 0; j < 8; j++) mma16816(sv[j], ql[t], &bf_[j >> 1][(j & 1) * 2]);
#pragma unroll
            for (int p = 0; p < 4; p++) ldmx4(bf_[p], kl_s + offs[p]);
#pragma unroll
            for (int j = 0; j < 8; j++) mma16816(sv[j], qh[t], &bf_[j >> 1][(j & 1) * 2]);
        }

        // ---- online softmax (rows r0 = d0,d1; r0+8 = d2,d3; reduce over quad)
        float mx0 = sv[0][0], mx1 = sv[0][2];
#pragma unroll
        for (int j = 0; j < 8; j++) {
            mx0 = fmaxf(mx0, fmaxf(sv[j][0], sv[j][1]));
            mx1 = fmaxf(mx1, fmaxf(sv[j][2], sv[j][3]));
        }
        mx0 = fmaxf(mx0, __shfl_xor_sync(0xffffffffu, mx0, 1));
        mx0 = fmaxf(mx0, __shfl_xor_sync(0xffffffffu, mx0, 2));
        mx1 = fmaxf(mx1, __shfl_xor_sync(0xffffffffu, mx1, 1));
        mx1 = fmaxf(mx1, __shfl_xor_sync(0xffffffffu, mx1, 2));
        float mn0 = fmaxf(m0, mx0), mn1 = fmaxf(m1, mx1);
        float al0 = __expf(m0 - mn0), al1 = __expf(m1 - mn1);
        m0 = mn0; m1 = mn1;
        float s0 = 0.0f, s1 = 0.0f;
#pragma unroll
        for (int j = 0; j < 8; j++) {
            sv[j][0] = __expf(sv[j][0] - mn0); s0 += sv[j][0];
            sv[j][1] = __expf(sv[j][1] - mn0); s0 += sv[j][1];
            sv[j][2] = __expf(sv[j][2] - mn1); s1 += sv[j][2];
            sv[j][3] = __expf(sv[j][3] - mn1); s1 += sv[j][3];
        }
        s0 += __shfl_xor_sync(0xffffffffu, s0, 1);
        s0 += __shfl_xor_sync(0xffffffffu, s0, 2);
        s1 += __shfl_xor_sync(0xffffffffu, s1, 1);
        s1 += __shfl_xor_sync(0xffffffffu, s1, 2);
        l0 = l0 * al0 + s0;
        l1 = l1 * al1 + s1;
#pragma unroll
        for (int j = 0; j < 8; j++) {
            oa[j][0] *= al0; oa[j][1] *= al0;
            oa[j][2] *= al1; oa[j][3] *= al1;
        }

        // ---- O += P V (3-term); P built from sv fragments in registers
#pragma unroll
        for (int t = 0; t < 4; t++) {
            uint32_t ph[4], pl[4];
            split2(sv[2 * t][0], sv[2 * t][1], ph[0], pl[0]);
            split2(sv[2 * t][2], sv[2 * t][3], ph[1], pl[1]);
            split2(sv[2 * t + 1][0], sv[2 * t + 1][1], ph[2], pl[2]);
            split2(sv[2 * t + 1][2], sv[2 * t + 1][3], ph[3], pl[3]);
            uint32_t vf[4][4];
            uint32_t offs[4];
#pragma unroll
            for (int p = 0; p < 4; p++) {
                uint32_t off = (uint32_t)((p * 16 + b_row) * 128 + t * 32 + b_kb);
                off ^= (off >> 3) & 0x70;
                offs[p] = off;
                ldmx4(vf[p], vh_s + off);
            }
#pragma unroll
            for (int j = 0; j < 8; j++) mma16816(oa[j], ph, &vf[j >> 1][(j & 1) * 2]);
#pragma unroll
            for (int j = 0; j < 8; j++) mma16816(oa[j], pl, &vf[j >> 1][(j & 1) * 2]);
#pragma unroll
            for (int p = 0; p < 4; p++) ldmx4(vf[p], vl_s + offs[p]);
#pragma unroll
            for (int j = 0; j < 8; j++) mma16816(oa[j], ph, &vf[j >> 1][(j & 1) * 2]);
        }
        __syncthreads();
    }

    // ---- epilogue: normalize, split, write to g_xhi/g_xlo in [b,s,d]
    float inv0 = 1.0f / l0, inv1 = 1.0f / l1;
    int bb = bh >> 4, h = bh & 15;
    int r0g = q0 + warp * 16 + (lane >> 2);
    int c0 = (lane & 3) * 2;
#pragma unroll
    for (int j = 0; j < 8; j++) {
        int hd = j * 8 + c0;
        uint32_t hi, lo;
        split2(oa[j][0] * inv0, oa[j][1] * inv0, hi, lo);
        size_t i0 = ((size_t)(bb * SEQ + r0g)) * DMODEL + h * HDIM + hd;
        *(uint32_t*)&g_xhi[i0] = hi;
        *(uint32_t*)&g_xlo[i0] = lo;
        split2(oa[j][2] * inv1, oa[j][3] * inv1, hi, lo);
        size_t i1 = i0 + (size_t)8 * DMODEL;
        *(uint32_t*)&g_xhi[i1] = hi;
        *(uint32_t*)&g_xlo[i1] = lo;
    }
}

// ===================== launch =====================
extern "C" void kernel_launch(void* const* d_in, const int* in_sizes, int n_in,
                              void* d_out, int out_size) {
    (void)in_sizes; (void)n_in; (void)out_size;
    const float* x  = (const float*)d_in[0];
    const float* Wq = (const float*)d_in[1];
    const float* bq = (const float*)d_in[2];
    const float* Wk = (const float*)d_in[3];
    const float* bk = (const float*)d_in[4];
    const float* Wv = (const float*)d_in[5];
    const float* bv = (const float*)d_in[6];
    const float* Wo = (const float*)d_in[7];
    const float* bo = (const float*)d_in[8];
    float* out = (float*)d_out;

    cudaFuncSetAttribute(k_mm, cudaFuncAttributeMaxDynamicSharedMemorySize, MM_SMEM);
    cudaFuncSetAttribute(k_flash2, cudaFuncAttributeMaxDynamicSharedMemorySize, FL2_SMEM);

    k_init_freq<<<1, 512>>>();
    k_pe_split<<<dim3(SEQ / 32, DMODEL / 32, BATCH), dim3(32, 8)>>>(x);
    k_split_w<<<1024, 256>>>(Wq, 0);
    k_split_w<<<1024, 256>>>(Wk, 1);
    k_split_w<<<1024, 256>>>(Wv, 2);
    k_split_w<<<1024, 256>>>(Wo, 3);

    dim3 ggrid(DMODEL / 128, NTOK / 128);
    k_mm<<<ggrid, 256, MM_SMEM>>>(0, bq, nullptr, 0);
    k_mm<<<ggrid, 256, MM_SMEM>>>(1, bk, nullptr, 1);
    k_mm<<<ggrid, 256, MM_SMEM>>>(2, bv, nullptr, 2);

    k_flash2<<<dim3(SEQ / 128, BATCH * NHEAD), 256, FL2_SMEM>>>();

    k_mm<<<ggrid, 256, MM_SMEM>>>(3, bo, out, 3);
}

// round 11
// speedup vs baseline: 5.4344x; 1.2084x over previous
#include <cuda_runtime.h>
#include <cuda_bf16.h>
#include <cstdint>
#include <math.h>

#define BATCH 4
#define DMODEL 1024
#define SEQ 2048
#define NHEAD 16
#define HDIM 64
#define NTOK (BATCH * SEQ)   // 8192

// ===================== device scratch (no allocation) =====================
__device__ float g_freq[DMODEL / 2];
__device__ __align__(16) __nv_bfloat16 g_xhi[(size_t)NTOK * DMODEL];  // x+PE hi; later attn-out hi
__device__ __align__(16) __nv_bfloat16 g_xlo[(size_t)NTOK * DMODEL];  // x+PE lo; later attn-out lo
__device__ __align__(16) __nv_bfloat16 g_whi[4][(size_t)DMODEL * DMODEL];
__device__ __align__(16) __nv_bfloat16 g_wlo[4][(size_t)DMODEL * DMODEL];
// bf16 hi/lo Q,K ([bh][s][hd], Q pre-scaled by 0.125) and V transposed ([bh][hd][s])
__device__ __align__(16) __nv_bfloat16 g_qhi[(size_t)NTOK * DMODEL];
__device__ __align__(16) __nv_bfloat16 g_qlo[(size_t)NTOK * DMODEL];
__device__ __align__(16) __nv_bfloat16 g_khi[(size_t)NTOK * DMODEL];
__device__ __align__(16) __nv_bfloat16 g_klo[(size_t)NTOK * DMODEL];
__device__ __align__(16) __nv_bfloat16 g_vthi[(size_t)NTOK * DMODEL];
__device__ __align__(16) __nv_bfloat16 g_vtlo[(size_t)NTOK * DMODEL];

// ===================== PTX helpers (family-agnostic) =====================
__device__ __forceinline__ uint32_t smem_u32(const void* p) {
    uint32_t a;
    asm("{ .reg .u64 t; cvta.to.shared.u64 t, %1; cvt.u32.u64 %0, t; }" : "=r"(a) : "l"(p));
    return a;
}
__device__ __forceinline__ void ldmx4(uint32_t* r, uint32_t addr) {
    asm volatile("ldmatrix.sync.aligned.m8n8.x4.shared.b16 {%0,%1,%2,%3}, [%4];"
                 : "=r"(r[0]), "=r"(r[1]), "=r"(r[2]), "=r"(r[3]) : "r"(addr));
}
__device__ __forceinline__ void mma16816(float* d, const uint32_t* a, const uint32_t* b) {
    asm volatile("mma.sync.aligned.m16n8k16.row.col.f32.bf16.bf16.f32 "
                 "{%0,%1,%2,%3}, {%4,%5,%6,%7}, {%8,%9}, {%0,%1,%2,%3};"
                 : "+f"(d[0]), "+f"(d[1]), "+f"(d[2]), "+f"(d[3])
                 : "r"(a[0]), "r"(a[1]), "r"(a[2]), "r"(a[3]), "r"(b[0]), "r"(b[1]));
}
__device__ __forceinline__ void cpa16(uint32_t saddr, const void* g) {
    asm volatile("cp.async.cg.shared.global [%0], [%1], 16;" :: "r"(saddr), "l"(g));
}
#define CP_COMMIT asm volatile("cp.async.commit_group;" ::: "memory")
#define CP_WAIT1 asm volatile("cp.async.wait_group 1;" ::: "memory")
#define CP_WAIT0 asm volatile("cp.async.wait_group 0;" ::: "memory")

// split fp32 pair into packed bf16x2 hi and lo (low half = first arg)
__device__ __forceinline__ void split2(float x0, float x1, uint32_t& hi, uint32_t& lo) {
    __nv_bfloat162 h = __floats2bfloat162_rn(x0, x1);
    hi = *(uint32_t*)&h;
    float r0 = x0 - __bfloat162float(h.x);
    float r1 = x1 - __bfloat162float(h.y);
    __nv_bfloat162 l = __floats2bfloat162_rn(r0, r1);
    lo = *(uint32_t*)&l;
}

// ===================== prep kernels =====================
__global__ void k_init_freq() {
    int i = threadIdx.x;
    if (i < DMODEL / 2)
        g_freq[i] = (float)exp(-(double)(2 * i) * (9.210340371976184 / 1024.0));
}

// x + PE, transpose [B,D,S] -> [B,S,D], write bf16 hi/lo split
__global__ void k_pe_split(const float* __restrict__ x) {
    __shared__ float tile[32][33];
    int b = blockIdx.z, d0 = blockIdx.y * 32, s0 = blockIdx.x * 32;
    int txx = threadIdx.x, tyy = threadIdx.y;
    const float* xb = x + (size_t)b * DMODEL * SEQ;
#pragma unroll
    for (int r = 0; r < 4; r++) {
        int d = d0 + tyy + r * 8, s = s0 + txx;
        float ang = (float)s * g_freq[d >> 1];
        float pe = (d & 1) ? cosf(ang) : sinf(ang);
        tile[tyy + r * 8][txx] = xb[(size_t)d * SEQ + s] + pe;
    }
    __syncthreads();
#pragma unroll
    for (int r = 0; r < 4; r++) {
        int sl = tyy + r * 8;
        float v = tile[txx][sl];
        __nv_bfloat16 hi = __float2bfloat16(v);
        float lo = v - __bfloat162float(hi);
        size_t idx = ((size_t)b * SEQ + s0 + sl) * DMODEL + d0 + txx;
        g_xhi[idx] = hi;
        g_xlo[idx] = __float2bfloat16(lo);
    }
}

// Split all four weight matrices into bf16 hi/lo (one launch)
__global__ void k_split_w4(const float* __restrict__ w0, const float* __restrict__ w1,
                           const float* __restrict__ w2, const float* __restrict__ w3) {
    int wsel = blockIdx.x >> 10;
    const float* w = (wsel == 0) ? w0 : (wsel == 1) ? w1 : (wsel == 2) ? w2 : w3;
    int i = ((blockIdx.x & 1023) * 256 + threadIdx.x) * 4;
    float4 v = *(const float4*)(w + i);
    __nv_bfloat16* hi = g_whi[wsel];
    __nv_bfloat16* lo = g_wlo[wsel];
    float a[4] = {v.x, v.y, v.z, v.w};
#pragma unroll
    for (int j = 0; j < 4; j++) {
        __nv_bfloat16 h = __float2bfloat16(a[j]);
        hi[i + j] = h;
        lo[i + j] = __float2bfloat16(a[j] - __bfloat162float(h));
    }
}

// ===================== HMMA GEMM: C[8192,1024] = A * W^T + bias ==============
// Composite chunks: {Ahi, Alo, Whi, Wlo} x 64-K slice per chunk (64KB), 16 chunks.
// 3-term split: Ahi*Whi + Ahi*Wlo + Alo*Whi; fp32 register accumulators.
// 3-stage cp.async pipeline (192KB smem), ONE __syncthreads per chunk.
// 8 warps as 2(M) x 4(N): warp tile 64x32, 4x4 m16n8 fragments.
#define MM_STG 65536u
#define MM_SMEM (3 * 65536)

__global__ __launch_bounds__(256) void k_mm(int wsel,
                                            const float* __restrict__ bias,
                                            float* __restrict__ outp,
                                            int which) {
    extern __shared__ char smem[];
    uint32_t sb = smem_u32(smem);
    int tid = threadIdx.x;
    int warp = tid >> 5, lane = tid & 31;
    int wm = warp & 1, wn = warp >> 1;
    int n0 = blockIdx.x * 128, m0 = blockIdx.y * 128;

    const __nv_bfloat16* WH = g_whi[wsel];
    const __nv_bfloat16* WL = g_wlo[wsel];

    float acc[4][4][4];
#pragma unroll
    for (int mt = 0; mt < 4; mt++)
#pragma unroll
        for (int nt = 0; nt < 4; nt++)
#pragma unroll
            for (int e = 0; e < 4; e++) acc[mt][nt][e] = 0.0f;

    // staging: thread -> (row = it*32 + tid>>3, col16B = tid&7), SW128 swizzle
    int ldr = tid >> 3, ldc = tid & 7;

#define MM_ISSUE(kcv, st) do {                                                      \
        uint32_t bs = sb + (uint32_t)(st) * MM_STG;                                 \
        int _kc = (kcv);                                                            \
        _Pragma("unroll") for (int it = 0; it < 4; it++) {                          \
            int row = it * 32 + ldr;                                                \
            uint32_t off = (uint32_t)(row * 128 + ldc * 16);                        \
            off ^= (off >> 3) & 0x70;                                               \
            size_t ga = (size_t)(m0 + row) * DMODEL + _kc * 64 + ldc * 8;           \
            size_t gb = (size_t)(n0 + row) * DMODEL + _kc * 64 + ldc * 8;           \
            cpa16(bs + off,          g_xhi + ga);                                   \
            cpa16(bs + 16384 + off,  g_xlo + ga);                                   \
            cpa16(bs + 32768 + off,  WH + gb);                                      \
            cpa16(bs + 49152 + off,  WL + gb);                                      \
        }                                                                           \
        CP_COMMIT;                                                                  \
    } while (0)

    // per-thread ldmatrix row/byte components (canonical m16n8k16 fragments)
    int a_row = wm * 64 + (lane & 15);                         // + mt*16
    int a_kb = (lane >> 4) * 16;                               // + k16*32
    int b_row = wn * 32 + (lane & 7) + ((lane >> 4) & 1) * 8;  // + ntp*16
    int b_kb = ((lane >> 3) & 1) * 16;

    MM_ISSUE(0, 0);
    MM_ISSUE(1, 1);

#pragma unroll 1
    for (int kc = 0; kc < 16; kc++) {
        int st = kc % 3;
        if (kc + 1 < 16) CP_WAIT1; else CP_WAIT0;   // this thread's chunk kc arrived
        __syncthreads();                             // visible to all; stage (kc-1)%3 free
        if (kc + 2 < 16) MM_ISSUE(kc + 2, (kc + 2) % 3);
        uint32_t AH = sb + (uint32_t)st * MM_STG;
        uint32_t AL = AH + 16384u, BH = AH + 32768u, BL = AH + 49152u;
#pragma unroll
        for (int k16 = 0; k16 < 4; k16++) {
            int kbyte = k16 * 32;
            uint32_t ah[4][4], al[4][4], bh[2][4], bl[2][4];
#pragma unroll
            for (int mt = 0; mt < 4; mt++) {
                uint32_t off = (uint32_t)((a_row + mt * 16) * 128 + kbyte + a_kb);
                off ^= (off >> 3) & 0x70;
                ldmx4(ah[mt], AH + off);
                ldmx4(al[mt], AL + off);
            }
#pragma unroll
            for (int p = 0; p < 2; p++) {
                uint32_t off = (uint32_t)((b_row + p * 16) * 128 + kbyte + b_kb);
                off ^= (off >> 3) & 0x70;
                ldmx4(bh[p], BH + off);
                ldmx4(bl[p], BL + off);
            }
#pragma unroll
            for (int mt = 0; mt < 4; mt++)
#pragma unroll
                for (int nt = 0; nt < 4; nt++) {
                    mma16816(acc[mt][nt], ah[mt], &bh[nt >> 1][(nt & 1) * 2]);
                    mma16816(acc[mt][nt], ah[mt], &bl[nt >> 1][(nt & 1) * 2]);
                    mma16816(acc[mt][nt], al[mt], &bh[nt >> 1][(nt & 1) * 2]);
                }
        }
    }

    // ---- epilogue: d0,d1 -> (r0, c0..c0+1); d2,d3 -> (r0+8, ..)
    int r0 = lane >> 2, c0 = (lane & 3) * 2;
    int mbase = m0 + wm * 64, nbase = n0 + wn * 32;
    if (which <= 1) {
        // Q (scaled 0.125) or K -> bf16 hi/lo in [bh][s][hd]
        __nv_bfloat16* HI = which ? g_khi : g_qhi;
        __nv_bfloat16* LO = which ? g_klo : g_qlo;
        float scale = which ? 1.0f : 0.125f;
#pragma unroll
        for (int mt = 0; mt < 4; mt++)
#pragma unroll
            for (int half = 0; half < 2; half++) {
                int row = mbase + mt * 16 + r0 + half * 8;
                int bb2 = row >> 11;
                int sq = row & (SEQ - 1);
#pragma unroll
                for (int nt = 0; nt < 4; nt++) {
                    int jg = nbase + nt * 8 + c0;
                    int h = jg >> 6, hd = jg & 63;
                    float v0 = (acc[mt][nt][half * 2 + 0] + bias[jg + 0]) * scale;
                    float v1 = (acc[mt][nt][half * 2 + 1] + bias[jg + 1]) * scale;
                    uint32_t hi, lo;
                    split2(v0, v1, hi, lo);
                    size_t idx = ((size_t)(bb2 * NHEAD + h) * SEQ + sq) * HDIM + hd;
                    *(uint32_t*)&HI[idx] = hi;
                    *(uint32_t*)&LO[idx] = lo;
                }
            }
    } else if (which == 2) {
        // V -> bf16 hi/lo transposed [bh][hd][s]
#pragma unroll
        for (int mt = 0; mt < 4; mt++)
#pragma unroll
            for (int half = 0; half < 2; half++) {
                int row = mbase + mt * 16 + r0 + half * 8;
                int bb2 = row >> 11;
                int sq = row & (SEQ - 1);
#pragma unroll
                for (int nt = 0; nt < 4; nt++) {
                    int jg = nbase + nt * 8 + c0;
                    int h = jg >> 6, hd = jg & 63;
                    float v0 = acc[mt][nt][half * 2 + 0] + bias[jg + 0];
                    float v1 = acc[mt][nt][half * 2 + 1] + bias[jg + 1];
                    __nv_bfloat16 h0 = __float2bfloat16(v0);
                    __nv_bfloat16 h1 = __float2bfloat16(v1);
                    __nv_bfloat16 l0 = __float2bfloat16(v0 - __bfloat162float(h0));
                    __nv_bfloat16 l1 = __float2bfloat16(v1 - __bfloat162float(h1));
                    size_t tb = ((size_t)(bb2 * NHEAD + h) * HDIM + hd) * SEQ + sq;
                    g_vthi[tb] = h0; g_vtlo[tb] = l0;
                    g_vthi[tb + SEQ] = h1; g_vtlo[tb + SEQ] = l1;
                }
            }
    } else {
        // final projection: out[B, D, S]
#pragma unroll
        for (int mt = 0; mt < 4; mt++)
#pragma unroll
            for (int half = 0; half < 2; half++) {
                int row = mbase + mt * 16 + r0 + half * 8;
                int bb2 = row >> 11;
                int sq = row & (SEQ - 1);
#pragma unroll
                for (int nt = 0; nt < 4; nt++) {
                    int jg = nbase + nt * 8 + c0;
                    outp[((size_t)bb2 * DMODEL + jg) * SEQ + sq] =
                        acc[mt][nt][half * 2 + 0] + bias[jg];
                    outp[((size_t)bb2 * DMODEL + jg + 1) * SEQ + sq] =
                        acc[mt][nt][half * 2 + 1] + bias[jg + 1];
                }
            }
    }
}

// ===================== tensor-core flash attention =====================
// Br=128 (8 warps x m16), Bc=64. S = QhiKhi + QloKhi + QhiKlo (fp32 frags),
// softmax in fragments, P converted to bf16 hi/lo in registers (C->A layout match),
// O += PhiVhi + PloVhi + PhiVlo. K/V tiles cp.async double-buffered.
// smem: stage s at s*32768: KH 8K | KL 8K | VH 8K | VL 8K. Q staged at 0 in prologue.
#define FL2_SMEM 65536
__global__ __launch_bounds__(256) void k_flash2() {
    extern __shared__ char sm2[];
    uint32_t sb = smem_u32(sm2);
    int tid = threadIdx.x;
    int warp = tid >> 5, lane = tid & 31;
    int bh = blockIdx.y;
    int q0 = blockIdx.x * 128;

    const __nv_bfloat16* qh_g = g_qhi + ((size_t)bh * SEQ + q0) * HDIM;
    const __nv_bfloat16* ql_g = g_qlo + ((size_t)bh * SEQ + q0) * HDIM;
    const __nv_bfloat16* kh_g = g_khi + (size_t)bh * SEQ * HDIM;
    const __nv_bfloat16* kl_g = g_klo + (size_t)bh * SEQ * HDIM;
    const __nv_bfloat16* vh_g = g_vthi + (size_t)bh * HDIM * SEQ;
    const __nv_bfloat16* vl_g = g_vtlo + (size_t)bh * HDIM * SEQ;

    // ---- stage Q (hi @0, lo @16384), extract fragments, then free the space
#pragma unroll
    for (int it = 0; it < 4; it++) {
        int c = it * 256 + tid;
        int r = c >> 3, col = c & 7;
        uint32_t off = (uint32_t)(r * 128 + col * 16);
        off ^= (off >> 3) & 0x70;
        *(uint4*)(sm2 + off) = *(const uint4*)(qh_g + (size_t)r * HDIM + col * 8);
        *(uint4*)(sm2 + 16384 + off) = *(const uint4*)(ql_g + (size_t)r * HDIM + col * 8);
    }
    __syncthreads();
    uint32_t qh[4][4], ql[4][4];
    {
        int a_row = warp * 16 + (lane & 15);
        int a_kb = (lane >> 4) * 16;
#pragma unroll
        for (int t = 0; t < 4; t++) {
            uint32_t off = (uint32_t)(a_row * 128 + t * 32 + a_kb);
            off ^= (off >> 3) & 0x70;
            ldmx4(qh[t], sb + off);
            ldmx4(ql[t], sb + 16384 + off);
        }
    }
    __syncthreads();

    int b_row = (lane & 7) + ((lane >> 4) & 1) * 8;   // + pair*16
    int b_kb = ((lane >> 3) & 1) * 16;                // + t*32

#define FL_LOAD(s, kt) do {                                                     \
        uint32_t bs = sb + (uint32_t)(s) * 32768u;                              \
        int kb0 = (kt) * 64;                                                    \
        _Pragma("unroll") for (int it = 0; it < 2; it++) {                      \
            int c = it * 256 + tid;                                             \
            int r = c >> 3, col = c & 7;                                        \
            uint32_t off = (uint32_t)(r * 128 + col * 16);                      \
            off ^= (off >> 3) & 0x70;                                           \
            cpa16(bs + off, kh_g + (size_t)(kb0 + r) * HDIM + col * 8);         \
            cpa16(bs + 8192 + off, kl_g + (size_t)(kb0 + r) * HDIM + col * 8);  \
            cpa16(bs + 16384 + off, vh_g + (size_t)r * SEQ + kb0 + col * 8);    \
            cpa16(bs + 24576 + off, vl_g + (size_t)r * SEQ + kb0 + col * 8);    \
        }                                                                       \
    } while (0)

    float oa[8][4];
#pragma unroll
    for (int j = 0; j < 8; j++)
#pragma unroll
        for (int e = 0; e < 4; e++) oa[j][e] = 0.0f;
    float m0 = -1e30f, m1 = -1e30f, l0 = 0.0f, l1 = 0.0f;

    FL_LOAD(0, 0);
    CP_COMMIT;

#pragma unroll 1
    for (int kt = 0; kt < SEQ / 64; kt++) {
        int s = kt & 1;
        if (kt + 1 < SEQ / 64) {
            FL_LOAD(s ^ 1, kt + 1);
            CP_COMMIT;
            CP_WAIT1;
        } else {
            CP_WAIT0;
        }
        __syncthreads();
        uint32_t kh_s = sb + (uint32_t)s * 32768u;
        uint32_t kl_s = kh_s + 8192u, vh_s = kh_s + 16384u, vl_s = kh_s + 24576u;

        // ---- S = Q K^T (3-term)
        float sv[8][4];
#pragma unroll
        for (int j = 0; j < 8; j++)
#pragma unroll
            for (int e = 0; e < 4; e++) sv[j][e] = 0.0f;
#pragma unroll
        for (int t = 0; t < 4; t++) {
            uint32_t bf_[4][4];
            uint32_t offs[4];
#pragma unroll
            for (int p = 0; p < 4; p++) {
                uint32_t off = (uint32_t)((p * 16 + b_row) * 128 + t * 32 + b_kb);
                off ^= (off >> 3) & 0x70;
                offs[p] = off;
                ldmx4(bf_[p], kh_s + off);
            }
#pragma unroll
            for (int j = 0; j < 8; j++) mma16816(sv[j], qh[t], &bf_[j >> 1][(j & 1) * 2]);
#pragma unroll
            for (int j = 0; j < 8; j++) mma16816(sv[j], ql[t], &bf_[j >> 1][(j & 1) * 2]);
#pragma unroll
            for (int p = 0; p < 4; p++) ldmx4(bf_[p], kl_s + offs[p]);
#pragma unroll
            for (int j = 0; j < 8; j++) mma16816(sv[j], qh[t], &bf_[j >> 1][(j & 1) * 2]);
        }

        // ---- online softmax (rows r0 = d0,d1; r0+8 = d2,d3; reduce over quad)
        float mx0 = sv[0][0], mx1 = sv[0][2];
#pragma unroll
        for (int j = 0; j < 8; j++) {
            mx0 = fmaxf(mx0, fmaxf(sv[j][0], sv[j][1]));
            mx1 = fmaxf(mx1, fmaxf(sv[j][2], sv[j][3]));
        }
        mx0 = fmaxf(mx0, __shfl_xor_sync(0xffffffffu, mx0, 1));
        mx0 = fmaxf(mx0, __shfl_xor_sync(0xffffffffu, mx0, 2));
        mx1 = fmaxf(mx1, __shfl_xor_sync(0xffffffffu, mx1, 1));
        mx1 = fmaxf(mx1, __shfl_xor_sync(0xffffffffu, mx1, 2));
        float mn0 = fmaxf(m0, mx0), mn1 = fmaxf(m1, mx1);
        float al0 = __expf(m0 - mn0), al1 = __expf(m1 - mn1);
        m0 = mn0; m1 = mn1;
        float s0 = 0.0f, s1 = 0.0f;
#pragma unroll
        for (int j = 0; j < 8; j++) {
            sv[j][0] = __expf(sv[j][0] - mn0); s0 += sv[j][0];
            sv[j][1] = __expf(sv[j][1] - mn0); s0 += sv[j][1];
            sv[j][2] = __expf(sv[j][2] - mn1); s1 += sv[j][2];
            sv[j][3] = __expf(sv[j][3] - mn1); s1 += sv[j][3];
        }
        s0 += __shfl_xor_sync(0xffffffffu, s0, 1);
        s0 += __shfl_xor_sync(0xffffffffu, s0, 2);
        s1 += __shfl_xor_sync(0xffffffffu, s1, 1);
        s1 += __shfl_xor_sync(0xffffffffu, s1, 2);
        l0 = l0 * al0 + s0;
        l1 = l1 * al1 + s1;
#pragma unroll
        for (int j = 0; j < 8; j++) {
            oa[j][0] *= al0; oa[j][1] *= al0;
            oa[j][2] *= al1; oa[j][3] *= al1;
        }

        // ---- O += P V (3-term); P built from sv fragments in registers
#pragma unroll
        for (int t = 0; t < 4; t++) {
            uint32_t ph[4], pl[4];
            split2(sv[2 * t][0], sv[2 * t][1], ph[0], pl[0]);
            split2(sv[2 * t][2], sv[2 * t][3], ph[1], pl[1]);
            split2(sv[2 * t + 1][0], sv[2 * t + 1][1], ph[2], pl[2]);
            split2(sv[2 * t + 1][2], sv[2 * t + 1][3], ph[3], pl[3]);
            uint32_t vf[4][4];
            uint32_t offs[4];
#pragma unroll
            for (int p = 0; p < 4; p++) {
                uint32_t off = (uint32_t)((p * 16 + b_row) * 128 + t * 32 + b_kb);
                off ^= (off >> 3) & 0x70;
                offs[p] = off;
                ldmx4(vf[p], vh_s + off);
            }
#pragma unroll
            for (int j = 0; j < 8; j++) mma16816(oa[j], ph, &vf[j >> 1][(j & 1) * 2]);
#pragma unroll
            for (int j = 0; j < 8; j++) mma16816(oa[j], pl, &vf[j >> 1][(j & 1) * 2]);
#pragma unroll
            for (int p = 0; p < 4; p++) ldmx4(vf[p], vl_s + offs[p]);
#pragma unroll
            for (int j = 0; j < 8; j++) mma16816(oa[j], ph, &vf[j >> 1][(j & 1) * 2]);
        }
        __syncthreads();
    }

    // ---- epilogue: normalize, split, write to g_xhi/g_xlo in [b,s,d]
    float inv0 = 1.0f / l0, inv1 = 1.0f / l1;
    int bb = bh >> 4, h = bh & 15;
    int r0g = q0 + warp * 16 + (lane >> 2);
    int c0 = (lane & 3) * 2;
#pragma unroll
    for (int j = 0; j < 8; j++) {
        int hd = j * 8 + c0;
        uint32_t hi, lo;
        split2(oa[j][0] * inv0, oa[j][1] * inv0, hi, lo);
        size_t i0 = ((size_t)(bb * SEQ + r0g)) * DMODEL + h * HDIM + hd;
        *(uint32_t*)&g_xhi[i0] = hi;
        *(uint32_t*)&g_xlo[i0] = lo;
        split2(oa[j][2] * inv1, oa[j][3] * inv1, hi, lo);
        size_t i1 = i0 + (size_t)8 * DMODEL;
        *(uint32_t*)&g_xhi[i1] = hi;
        *(uint32_t*)&g_xlo[i1] = lo;
    }
}

// ===================== launch =====================
extern "C" void kernel_launch(void* const* d_in, const int* in_sizes, int n_in,
                              void* d_out, int out_size) {
    (void)in_sizes; (void)n_in; (void)out_size;
    const float* x  = (const float*)d_in[0];
    const float* Wq = (const float*)d_in[1];
    const float* bq = (const float*)d_in[2];
    const float* Wk = (const float*)d_in[3];
    const float* bk = (const float*)d_in[4];
    const float* Wv = (const float*)d_in[5];
    const float* bv = (const float*)d_in[6];
    const float* Wo = (const float*)d_in[7];
    const float* bo = (const float*)d_in[8];
    float* out = (float*)d_out;

    cudaFuncSetAttribute(k_mm, cudaFuncAttributeMaxDynamicSharedMemorySize, MM_SMEM);
    cudaFuncSetAttribute(k_flash2, cudaFuncAttributeMaxDynamicSharedMemorySize, FL2_SMEM);

    k_init_freq<<<1, 512>>>();
    k_pe_split<<<dim3(SEQ / 32, DMODEL / 32, BATCH), dim3(32, 8)>>>(x);
    k_split_w4<<<4096, 256>>>(Wq, Wk, Wv, Wo);

    dim3 ggrid(DMODEL / 128, NTOK / 128);
    k_mm<<<ggrid, 256, MM_SMEM>>>(0, bq, nullptr, 0);
    k_mm<<<ggrid, 256, MM_SMEM>>>(1, bk, nullptr, 1);
    k_mm<<<ggrid, 256, MM_SMEM>>>(2, bv, nullptr, 2);

    k_flash2<<<dim3(SEQ / 128, BATCH * NHEAD), 256, FL2_SMEM>>>();

    k_mm<<<ggrid, 256, MM_SMEM>>>(3, bo, out, 3);
}